// round 7
// baseline (speedup 1.0000x reference)
#include <cuda_runtime.h>
#include <cuda_bf16.h>

// Scratch (allocation-free rule: __device__ globals).
#define MAX_S 262144
#define MAX_N 2097152
__device__ int      g_count[MAX_S];
__device__ int      g_base[MAX_S];
__device__ int      g_cursor[MAX_S];
__device__ unsigned g_last[MAX_S];    // bit pattern of segment-max timestamp (all t > 0)
__device__ int      g_perm[MAX_N];    // row indices grouped by segment

#define BETA 0.8f

// ---------------------------------------------------------------------------
__global__ void twma_init_kernel(int S) {
    int i = blockIdx.x * blockDim.x + threadIdx.x;
    if (i < S) {
        g_count[i] = 0;
        g_last[i]  = 0u;
    }
}

// ---------------------------------------------------------------------------
// Histogram of segment ids + segment-max of timestamps, 4 rows per thread
// (uint order == float order since all t > 0; init 0 => empty segments output
// last_t = 0, matching the reference's where(tw>0, last_t, 0)).
__global__ void twma_hist_kernel(const int*   __restrict__ ids,
                                 const float* __restrict__ ts,
                                 int N) {
    int q = blockIdx.x * blockDim.x + threadIdx.x;
    int i0 = q * 4;
    if (i0 + 3 < N) {
        int4   s4 = *reinterpret_cast<const int4*>(ids + i0);
        float4 t4 = *reinterpret_cast<const float4*>(ts + i0);
        atomicAdd(&g_count[s4.x], 1); atomicMax(&g_last[s4.x], __float_as_uint(t4.x));
        atomicAdd(&g_count[s4.y], 1); atomicMax(&g_last[s4.y], __float_as_uint(t4.y));
        atomicAdd(&g_count[s4.z], 1); atomicMax(&g_last[s4.z], __float_as_uint(t4.z));
        atomicAdd(&g_count[s4.w], 1); atomicMax(&g_last[s4.w], __float_as_uint(t4.w));
    } else {
        for (int i = i0; i < N; i++) {
            atomicAdd(&g_count[ids[i]], 1);
            atomicMax(&g_last[ids[i]], __float_as_uint(ts[i]));
        }
    }
}

// ---------------------------------------------------------------------------
// Single-block exclusive scan of g_count -> g_base (+ g_cursor copy).
// 1024 threads, ceil(S/1024) elements each. Two passes over L2-resident data:
// per-thread sum -> shuffle block scan -> prefix write.
__global__ void twma_scan_kernel(int S) {
    const int tid  = threadIdx.x;               // 1024 threads
    const int per  = (S + 1023) >> 10;          // elems per thread (64 for 64K)
    const int base = tid * per;
    const bool vec = ((per & 3) == 0) && ((S & 3) == 0);

    // Pass 1: per-thread sum.
    int sum = 0;
    if (vec) {
        for (int k = 0; k < per; k += 4) {
            if (base + k < S) {
                int4 v = *reinterpret_cast<const int4*>(&g_count[base + k]);
                sum += v.x + v.y + v.z + v.w;
            }
        }
    } else {
        for (int k = 0; k < per; k++)
            if (base + k < S) sum += g_count[base + k];
    }

    // Block exclusive scan of the 1024 per-thread sums.
    __shared__ int warp_tot[32];
    int lane = tid & 31, wid = tid >> 5;
    int s = sum;
    #pragma unroll
    for (int off = 1; off < 32; off <<= 1) {
        int t = __shfl_up_sync(0xffffffffu, s, off);
        if (lane >= off) s += t;
    }
    if (lane == 31) warp_tot[wid] = s;
    __syncthreads();
    if (wid == 0) {
        int v = warp_tot[lane];
        int ss = v;
        #pragma unroll
        for (int off = 1; off < 32; off <<= 1) {
            int t = __shfl_up_sync(0xffffffffu, ss, off);
            if (lane >= off) ss += t;
        }
        warp_tot[lane] = ss - v;                // exclusive warp prefix
    }
    __syncthreads();
    int run = warp_tot[wid] + (s - sum);        // exclusive prefix for thread

    // Pass 2: write exclusive prefixes (g_count re-read hits L2).
    if (vec) {
        for (int k = 0; k < per; k += 4) {
            if (base + k < S) {
                int4 v = *reinterpret_cast<const int4*>(&g_count[base + k]);
                int4 b;
                b.x = run; b.y = run + v.x; b.z = b.y + v.y; b.w = b.z + v.z;
                run = b.w + v.w;
                *reinterpret_cast<int4*>(&g_base[base + k])   = b;
                *reinterpret_cast<int4*>(&g_cursor[base + k]) = b;
            }
        }
    } else {
        for (int k = 0; k < per; k++) {
            int idx = base + k;
            if (idx < S) {
                g_base[idx]   = run;
                g_cursor[idx] = run;
                run += g_count[idx];
            }
        }
    }
}

// ---------------------------------------------------------------------------
// Bucket rows by segment, 4 rows per thread.
__global__ void twma_scatter_kernel(const int* __restrict__ ids, int N) {
    int q = blockIdx.x * blockDim.x + threadIdx.x;
    int i0 = q * 4;
    if (i0 + 3 < N) {
        int4 s4 = *reinterpret_cast<const int4*>(ids + i0);
        int p0 = atomicAdd(&g_cursor[s4.x], 1); g_perm[p0] = i0;
        int p1 = atomicAdd(&g_cursor[s4.y], 1); g_perm[p1] = i0 + 1;
        int p2 = atomicAdd(&g_cursor[s4.z], 1); g_perm[p2] = i0 + 2;
        int p3 = atomicAdd(&g_cursor[s4.w], 1); g_perm[p3] = i0 + 3;
    } else {
        for (int i = i0; i < N; i++) {
            int p = atomicAdd(&g_cursor[ids[i]], 1);
            g_perm[p] = i;
        }
    }
}

// ---------------------------------------------------------------------------
// One warp per (segment, 128-float column tile). Gather the segment's rows,
// accumulate w*m in registers, write agg = acc/tw and last_t exactly once.
// Each warp's message load: 32 lanes x float4 = 512B contiguous (coalesced).
// (R3 form — measured best; dependent perm->ts->exp chain is hidden by the
// ~870 resident warps per SM.)
__global__ void twma_seg_kernel(const float4* __restrict__ msg,
                                const float*  __restrict__ ts,
                                float* __restrict__ out,
                                int S, int C /* D/4 */, int D) {
    int gw   = (blockIdx.x * blockDim.x + threadIdx.x) >> 5;
    int lane = threadIdx.x & 31;
    int tilesPerSeg = C >> 5;                 // D/128 column tiles
    int seg  = gw / tilesPerSeg;
    int tile = gw - seg * tilesPerSeg;
    if (seg >= S) return;

    int      base = g_base[seg];
    int      cnt  = g_count[seg];
    unsigned lb   = g_last[seg];
    float    lt   = __uint_as_float(lb);
    int      col  = (tile << 5) + lane;       // float4 index within row

    float4 acc = make_float4(0.f, 0.f, 0.f, 0.f);
    float  tw  = 0.f;

    #pragma unroll 4
    for (int r = 0; r < cnt; r++) {
        int   i = g_perm[base + r];
        float w = __expf(BETA * (ts[i] - lt));   // broadcast loads, w in (0,1]
        tw += w;
        float4 m = msg[(long long)i * C + col];
        acc.x += w * m.x;
        acc.y += w * m.y;
        acc.z += w * m.z;
        acc.w += w * m.w;
    }

    float inv = (cnt > 0) ? (1.0f / tw) : 0.0f;
    reinterpret_cast<float4*>(out)[(long long)seg * C + col] =
        make_float4(acc.x * inv, acc.y * inv, acc.z * inv, acc.w * inv);

    if (tile == 0 && lane == 0) {
        out[(long long)S * D + seg] = __uint_as_float(lb);  // 0 for empty segs
    }
}

// ---------------------------------------------------------------------------
extern "C" void kernel_launch(void* const* d_in, const int* in_sizes, int n_in,
                              void* d_out, int out_size) {
    const float* msg = (const float*)d_in[0];   // [N, D] fp32
    const float* ts  = (const float*)d_in[1];   // [N]    fp32
    const int*   ids = (const int*)d_in[2];     // [N]    int32

    int N = in_sizes[1];
    int D = in_sizes[0] / N;          // 256
    int S = out_size / (D + 1);       // 65536 (out = S*D agg + S last_t)
    int C = D / 4;

    float* out = (float*)d_out;

    twma_init_kernel<<<(S + 255) / 256, 256>>>(S);

    int q = (N + 3) / 4;
    twma_hist_kernel<<<(q + 255) / 256, 256>>>(ids, ts, N);

    twma_scan_kernel<<<1, 1024>>>(S);

    twma_scatter_kernel<<<(q + 255) / 256, 256>>>(ids, N);

    long long warps   = (long long)S * (C >> 5); // one warp per (seg, 128-col tile)
    long long threads = warps * 32;
    unsigned blocks   = (unsigned)((threads + 255) / 256);
    twma_seg_kernel<<<blocks, 256>>>((const float4*)msg, ts, out, S, C, D);
}

// round 8
// speedup vs baseline: 1.1392x; 1.1392x over previous
#include <cuda_runtime.h>
#include <cuda_bf16.h>

// Scratch (allocation-free rule: __device__ globals).
#define MAX_S 262144
#define MAX_N 2097152
__device__ int      g_count[MAX_S];
__device__ int      g_base[MAX_S];    // block-local exclusive prefix (scan1)
__device__ int      g_cursor[MAX_S];  // running copy for scatter
__device__ int      g_bsum[1024];     // per-scan-block sums -> exclusive prefixes
__device__ unsigned g_last[MAX_S];    // bit pattern of segment-max timestamp (all t > 0)
__device__ int      g_perm[MAX_N];    // row indices grouped by segment

#define BETA 0.8f
#define SCAN_B 1024

// ---------------------------------------------------------------------------
// Histogram of segment ids + segment-max of timestamps (uint order == float
// order since all t > 0; init 0 => empty segments output last_t = 0, matching
// the reference's where(tw>0, last_t, 0)).  One row per thread (measured best:
// max thread count for atomic latency hiding).
__global__ void twma_hist_kernel(const int* __restrict__ ids,
                                 const float* __restrict__ ts,
                                 int N) {
    int i = blockIdx.x * blockDim.x + threadIdx.x;
    if (i < N) {
        int s = ids[i];
        atomicAdd(&g_count[s], 1);
        atomicMax(&g_last[s], __float_as_uint(ts[i]));
    }
}

// ---------------------------------------------------------------------------
// Per-block exclusive scan of g_count -> g_base/g_cursor (block-local), plus
// per-block total into g_bsum.  Final global base = g_base[i] + g_bsum[i>>10]
// (the bsum add is folded into the consumers; no third scan pass needed).
__global__ void twma_scan1_kernel(int S) {
    __shared__ int sh[SCAN_B];
    int tid = threadIdx.x;
    int gid = blockIdx.x * SCAN_B + tid;
    int v = (gid < S) ? g_count[gid] : 0;
    sh[tid] = v;
    __syncthreads();
    for (int off = 1; off < SCAN_B; off <<= 1) {
        int t = (tid >= off) ? sh[tid - off] : 0;
        __syncthreads();
        sh[tid] += t;
        __syncthreads();
    }
    int incl = sh[tid];
    if (gid < S) {
        int e = incl - v;               // block-local exclusive
        g_base[gid]   = e;
        g_cursor[gid] = e;
    }
    if (tid == SCAN_B - 1) g_bsum[blockIdx.x] = incl;
}

// Exclusive scan of the <=1024 block sums (single block).
__global__ void twma_scan2_kernel(int nb) {
    __shared__ int sh[SCAN_B];
    int tid = threadIdx.x;
    int v = (tid < nb) ? g_bsum[tid] : 0;
    sh[tid] = v;
    __syncthreads();
    for (int off = 1; off < SCAN_B; off <<= 1) {
        int t = (tid >= off) ? sh[tid - off] : 0;
        __syncthreads();
        sh[tid] += t;
        __syncthreads();
    }
    if (tid < nb) g_bsum[tid] = sh[tid] - v;      // exclusive
}

// ---------------------------------------------------------------------------
// Bucket rows by segment.  Global slot = block-local cursor + bsum prefix.
__global__ void twma_scatter_kernel(const int* __restrict__ ids, int N) {
    int i = blockIdx.x * blockDim.x + threadIdx.x;
    if (i < N) {
        int s = ids[i];
        int p = atomicAdd(&g_cursor[s], 1) + g_bsum[s >> 10];
        g_perm[p] = i;
    }
}

// ---------------------------------------------------------------------------
// One warp per (segment, 128-float column tile). Gather the segment's rows,
// accumulate w*m in registers, write agg = acc/tw and last_t exactly once.
// Each warp's message load: 32 lanes x float4 = 512B contiguous (coalesced).
// (R3 form — measured best; dependent perm->ts->exp chain is hidden by the
// ~870 resident warps per SM.)
__global__ void twma_seg_kernel(const float4* __restrict__ msg,
                                const float*  __restrict__ ts,
                                float* __restrict__ out,
                                int S, int C /* D/4 */, int D) {
    int gw   = (blockIdx.x * blockDim.x + threadIdx.x) >> 5;
    int lane = threadIdx.x & 31;
    int tilesPerSeg = C >> 5;                 // D/128 column tiles
    int seg  = gw / tilesPerSeg;
    int tile = gw - seg * tilesPerSeg;
    if (seg >= S) return;

    int      base = g_base[seg] + g_bsum[seg >> 10];
    int      cnt  = g_count[seg];
    unsigned lb   = g_last[seg];
    float    lt   = __uint_as_float(lb);
    int      col  = (tile << 5) + lane;       // float4 index within row

    float4 acc = make_float4(0.f, 0.f, 0.f, 0.f);
    float  tw  = 0.f;

    #pragma unroll 4
    for (int r = 0; r < cnt; r++) {
        int   i = g_perm[base + r];
        float w = __expf(BETA * (ts[i] - lt));   // broadcast loads, w in (0,1]
        tw += w;
        float4 m = msg[(long long)i * C + col];
        acc.x += w * m.x;
        acc.y += w * m.y;
        acc.z += w * m.z;
        acc.w += w * m.w;
    }

    float inv = (cnt > 0) ? (1.0f / tw) : 0.0f;
    reinterpret_cast<float4*>(out)[(long long)seg * C + col] =
        make_float4(acc.x * inv, acc.y * inv, acc.z * inv, acc.w * inv);

    if (tile == 0 && lane == 0) {
        out[(long long)S * D + seg] = __uint_as_float(lb);  // 0 for empty segs
    }
}

// ---------------------------------------------------------------------------
extern "C" void kernel_launch(void* const* d_in, const int* in_sizes, int n_in,
                              void* d_out, int out_size) {
    const float* msg = (const float*)d_in[0];   // [N, D] fp32
    const float* ts  = (const float*)d_in[1];   // [N]    fp32
    const int*   ids = (const int*)d_in[2];     // [N]    int32

    int N = in_sizes[1];
    int D = in_sizes[0] / N;          // 256
    int S = out_size / (D + 1);       // 65536 (out = S*D agg + S last_t)
    int C = D / 4;

    float* out = (float*)d_out;

    // Zero per-segment scratch via memset nodes (cheaper than a grid launch).
    void* p_count = nullptr;
    void* p_last  = nullptr;
    cudaGetSymbolAddress(&p_count, g_count);
    cudaGetSymbolAddress(&p_last,  g_last);
    cudaMemsetAsync(p_count, 0, (size_t)S * sizeof(int));
    cudaMemsetAsync(p_last,  0, (size_t)S * sizeof(unsigned));

    twma_hist_kernel<<<(N + 255) / 256, 256>>>(ids, ts, N);

    int nb = (S + SCAN_B - 1) / SCAN_B;         // 64 for S=65536 (<=1024)
    twma_scan1_kernel<<<nb, SCAN_B>>>(S);
    twma_scan2_kernel<<<1, SCAN_B>>>(nb);

    twma_scatter_kernel<<<(N + 255) / 256, 256>>>(ids, N);

    long long warps   = (long long)S * (C >> 5); // one warp per (seg, 128-col tile)
    long long threads = warps * 32;
    unsigned blocks   = (unsigned)((threads + 255) / 256);
    twma_seg_kernel<<<blocks, 256>>>((const float4*)msg, ts, out, S, C, D);
}

// round 10
// speedup vs baseline: 1.2248x; 1.0751x over previous
#include <cuda_runtime.h>
#include <cuda_bf16.h>

// Scratch (allocation-free rule: __device__ globals).
#define MAX_S 262144
#define MAX_N 2097152
__device__ int      g_head[MAX_S];    // per-segment list head (-1 = empty)
__device__ unsigned g_last[MAX_S];    // bit pattern of segment-max timestamp (all t > 0)
__device__ int      g_next[MAX_N];    // per-row list link (-1 = end)

#define BETA 0.8f

// ---------------------------------------------------------------------------
// Single pre-pass: build per-segment linked lists AND the segment-max of
// timestamps (uint order == float order since all t > 0; heads init to -1,
// last init to 0 => empty segments output last_t = 0, matching the
// reference's where(tw>0, last_t, 0)).  next[] writes are coalesced.
__global__ void twma_link_kernel(const int*   __restrict__ ids,
                                 const float* __restrict__ ts,
                                 int N) {
    int i = blockIdx.x * blockDim.x + threadIdx.x;
    if (i < N) {
        int s = ids[i];
        atomicMax(&g_last[s], __float_as_uint(ts[i]));
        g_next[i] = atomicExch(&g_head[s], i);
    }
}

// ---------------------------------------------------------------------------
// One warp per (segment, 128-float column tile). Walk the segment's list,
// accumulate w*m in registers, write agg = acc/tw and last_t exactly once.
// Each warp's message load: 32 lanes x float4 = 512B contiguous (coalesced).
// The serial next[] chase (~234cyc L2 per row per warp) is hidden under the
// chip-wide DRAM-bound message read.
__global__ void twma_seg_kernel(const float4* __restrict__ msg,
                                const float*  __restrict__ ts,
                                float* __restrict__ out,
                                int S, int C /* D/4 */, int D) {
    int gw   = (blockIdx.x * blockDim.x + threadIdx.x) >> 5;
    int lane = threadIdx.x & 31;
    int tilesPerSeg = C >> 5;                 // D/128 column tiles
    int seg  = gw / tilesPerSeg;
    int tile = gw - seg * tilesPerSeg;
    if (seg >= S) return;

    unsigned lb  = g_last[seg];
    float    lt  = __uint_as_float(lb);
    int      col = (tile << 5) + lane;        // float4 index within row

    float4 acc = make_float4(0.f, 0.f, 0.f, 0.f);
    float  tw  = 0.f;

    int i = g_head[seg];
    while (i >= 0) {
        int   nx = g_next[i];                 // issue the chase load first
        float w  = __expf(BETA * (ts[i] - lt));  // broadcast loads, w in (0,1]
        tw += w;
        float4 m = msg[(long long)i * C + col];
        acc.x += w * m.x;
        acc.y += w * m.y;
        acc.z += w * m.z;
        acc.w += w * m.w;
        i = nx;
    }

    float inv = (tw > 0.f) ? (1.0f / tw) : 0.0f;
    reinterpret_cast<float4*>(out)[(long long)seg * C + col] =
        make_float4(acc.x * inv, acc.y * inv, acc.z * inv, acc.w * inv);

    if (tile == 0 && lane == 0) {
        out[(long long)S * D + seg] = __uint_as_float(lb);  // 0 for empty segs
    }
}

// ---------------------------------------------------------------------------
extern "C" void kernel_launch(void* const* d_in, const int* in_sizes, int n_in,
                              void* d_out, int out_size) {
    const float* msg = (const float*)d_in[0];   // [N, D] fp32
    const float* ts  = (const float*)d_in[1];   // [N]    fp32
    const int*   ids = (const int*)d_in[2];     // [N]    int32

    int N = in_sizes[1];
    int D = in_sizes[0] / N;          // 256
    int S = out_size / (D + 1);       // 65536 (out = S*D agg + S last_t)
    int C = D / 4;

    float* out = (float*)d_out;

    // Init scratch: heads = -1 (0xFF bytes), last = 0.  Memset nodes only.
    void* p_head = nullptr;
    void* p_last = nullptr;
    cudaGetSymbolAddress(&p_head, g_head);
    cudaGetSymbolAddress(&p_last, g_last);
    cudaMemsetAsync(p_head, 0xFF, (size_t)S * sizeof(int));
    cudaMemsetAsync(p_last, 0,    (size_t)S * sizeof(unsigned));

    twma_link_kernel<<<(N + 255) / 256, 256>>>(ids, ts, N);

    long long warps   = (long long)S * (C >> 5); // one warp per (seg, 128-col tile)
    long long threads = warps * 32;
    unsigned blocks   = (unsigned)((threads + 255) / 256);
    twma_seg_kernel<<<blocks, 256>>>((const float4*)msg, ts, out, S, C, D);
}

// round 11
// speedup vs baseline: 1.3623x; 1.1122x over previous
#include <cuda_runtime.h>
#include <cuda_bf16.h>

// Scratch (allocation-free rule: __device__ globals).
#define MAX_S 262144
#define MAX_N 2097152
__device__ int      g_head[MAX_S];    // per-segment list head (-1 = empty)
__device__ unsigned g_last[MAX_S];    // bit pattern of segment-max timestamp (all t > 0)
__device__ int      g_next[MAX_N];    // per-row list link (-1 = end)

#define BETA 0.8f

// ---------------------------------------------------------------------------
// Single pre-pass: build per-segment linked lists AND the segment-max of
// timestamps (uint order == float order since all t > 0; heads init to -1,
// last init to 0 => empty segments output last_t = 0, matching the
// reference's where(tw>0, last_t, 0)).  next[] writes are coalesced.
__global__ void twma_link_kernel(const int*   __restrict__ ids,
                                 const float* __restrict__ ts,
                                 int N) {
    int i = blockIdx.x * blockDim.x + threadIdx.x;
    if (i < N) {
        int s = ids[i];
        atomicMax(&g_last[s], __float_as_uint(ts[i]));
        g_next[i] = atomicExch(&g_head[s], i);
    }
}

// ---------------------------------------------------------------------------
// One warp per SEGMENT, covering the full row with NC compile-time float4
// chunks per lane (NC=2 for D=256).  Single list walk per segment (vs one per
// column tile before): halves chase chains, ts loads, and exp work, and each
// chain link now unlocks NC independent 16B gathers per lane.
template <int NC>
__global__ void twma_seg_row_kernel(const float4* __restrict__ msg,
                                    const float*  __restrict__ ts,
                                    float* __restrict__ out,
                                    int S, int C /* = NC*32 */, int D) {
    int seg  = (blockIdx.x * blockDim.x + threadIdx.x) >> 5;
    if (seg >= S) return;
    int lane = threadIdx.x & 31;

    unsigned lb = g_last[seg];
    float    lt = __uint_as_float(lb);

    float4 acc[NC];
    #pragma unroll
    for (int j = 0; j < NC; j++) acc[j] = make_float4(0.f, 0.f, 0.f, 0.f);
    float tw = 0.f;

    int i = g_head[seg];
    while (i >= 0) {
        int nx = g_next[i];                   // issue the serial chase first
        const float4* row = msg + (long long)i * C + lane;
        float w = __expf(BETA * (ts[i] - lt));   // broadcast, w in (0,1]
        tw += w;
        #pragma unroll
        for (int j = 0; j < NC; j++) {
            float4 m = row[j * 32];           // NC independent gathers
            acc[j].x += w * m.x;
            acc[j].y += w * m.y;
            acc[j].z += w * m.z;
            acc[j].w += w * m.w;
        }
        i = nx;
    }

    float inv = (tw > 0.f) ? (1.0f / tw) : 0.0f;
    float4* dst = reinterpret_cast<float4*>(out) + (long long)seg * C + lane;
    #pragma unroll
    for (int j = 0; j < NC; j++) {
        dst[j * 32] = make_float4(acc[j].x * inv, acc[j].y * inv,
                                  acc[j].z * inv, acc[j].w * inv);
    }

    if (lane == 0) {
        out[(long long)S * D + seg] = __uint_as_float(lb);  // 0 for empty segs
    }
}

// ---------------------------------------------------------------------------
// Generic fallback: one warp per (segment, 128-float column tile), list walk
// per tile (measured-good R8 form).
__global__ void twma_seg_kernel(const float4* __restrict__ msg,
                                const float*  __restrict__ ts,
                                float* __restrict__ out,
                                int S, int C, int D) {
    int gw   = (blockIdx.x * blockDim.x + threadIdx.x) >> 5;
    int lane = threadIdx.x & 31;
    int tilesPerSeg = C >> 5;
    int seg  = gw / tilesPerSeg;
    int tile = gw - seg * tilesPerSeg;
    if (seg >= S) return;

    unsigned lb  = g_last[seg];
    float    lt  = __uint_as_float(lb);
    int      col = (tile << 5) + lane;

    float4 acc = make_float4(0.f, 0.f, 0.f, 0.f);
    float  tw  = 0.f;

    int i = g_head[seg];
    while (i >= 0) {
        int   nx = g_next[i];
        float w  = __expf(BETA * (ts[i] - lt));
        tw += w;
        float4 m = msg[(long long)i * C + col];
        acc.x += w * m.x;
        acc.y += w * m.y;
        acc.z += w * m.z;
        acc.w += w * m.w;
        i = nx;
    }

    float inv = (tw > 0.f) ? (1.0f / tw) : 0.0f;
    reinterpret_cast<float4*>(out)[(long long)seg * C + col] =
        make_float4(acc.x * inv, acc.y * inv, acc.z * inv, acc.w * inv);

    if (tile == 0 && lane == 0) {
        out[(long long)S * D + seg] = __uint_as_float(lb);
    }
}

// ---------------------------------------------------------------------------
extern "C" void kernel_launch(void* const* d_in, const int* in_sizes, int n_in,
                              void* d_out, int out_size) {
    const float* msg = (const float*)d_in[0];   // [N, D] fp32
    const float* ts  = (const float*)d_in[1];   // [N]    fp32
    const int*   ids = (const int*)d_in[2];     // [N]    int32

    int N = in_sizes[1];
    int D = in_sizes[0] / N;          // 256
    int S = out_size / (D + 1);       // 65536 (out = S*D agg + S last_t)
    int C = D / 4;

    float* out = (float*)d_out;

    // Init scratch: heads = -1 (0xFF bytes), last = 0.  Memset nodes only.
    void* p_head = nullptr;
    void* p_last = nullptr;
    cudaGetSymbolAddress(&p_head, g_head);
    cudaGetSymbolAddress(&p_last, g_last);
    cudaMemsetAsync(p_head, 0xFF, (size_t)S * sizeof(int));
    cudaMemsetAsync(p_last, 0,    (size_t)S * sizeof(unsigned));

    twma_link_kernel<<<(N + 255) / 256, 256>>>(ids, ts, N);

    if (C == 64) {
        // D=256: one warp per segment, 2 float4 chunks per lane.
        long long threads = (long long)S * 32;
        unsigned blocks = (unsigned)((threads + 255) / 256);
        twma_seg_row_kernel<2><<<blocks, 256>>>((const float4*)msg, ts, out,
                                                S, C, D);
    } else if (C == 32) {
        long long threads = (long long)S * 32;
        unsigned blocks = (unsigned)((threads + 255) / 256);
        twma_seg_row_kernel<1><<<blocks, 256>>>((const float4*)msg, ts, out,
                                                S, C, D);
    } else {
        long long warps   = (long long)S * (C >> 5);
        long long threads = warps * 32;
        unsigned blocks   = (unsigned)((threads + 255) / 256);
        twma_seg_kernel<<<blocks, 256>>>((const float4*)msg, ts, out, S, C, D);
    }
}